// round 15
// baseline (speedup 1.0000x reference)
#include <cuda_runtime.h>
#include <cuda_bf16.h>
#include <cuda_fp16.h>
#include <math.h>
#include <stdint.h>
#include <stddef.h>

#define T_DIM 2048
#define D_DIM 2048
#define H_DIM 16
#define C_DIM 128

// ---------------- scratch (device globals; no runtime allocation) ----------
__device__ __align__(128) float g_qkv[(size_t)T_DIM * 3 * D_DIM];
__device__ __align__(128) __half g_xh [(size_t)T_DIM * D_DIM];
__device__ __align__(128) __half g_xl [(size_t)T_DIM * D_DIM];
__device__ __align__(128) __half g_wa [(size_t)3 * D_DIM * D_DIM];
__device__ __align__(128) __half g_wp [(size_t)D_DIM * D_DIM];
__device__ __align__(128) __half g_aoh[(size_t)T_DIM * D_DIM];
__device__ __align__(128) __half g_aol[(size_t)T_DIM * D_DIM];
__device__ __align__(128) __nv_bfloat16 g_qh[(size_t)H_DIM * T_DIM * C_DIM];
__device__ __align__(128) __nv_bfloat16 g_ql[(size_t)H_DIM * T_DIM * C_DIM];
__device__ __align__(128) __nv_bfloat16 g_kh[(size_t)H_DIM * T_DIM * C_DIM];
__device__ __align__(128) __nv_bfloat16 g_kl[(size_t)H_DIM * T_DIM * C_DIM];
__device__ __align__(128) __nv_bfloat16 g_vh[(size_t)H_DIM * T_DIM * C_DIM];
__device__ __align__(128) __nv_bfloat16 g_vl[(size_t)H_DIM * T_DIM * C_DIM];

// ---------------- asm helpers ----------------------------------------------
__device__ __forceinline__ uint32_t smem_u32(const void* p) {
    return (uint32_t)__cvta_generic_to_shared(p);
}
__device__ __forceinline__ void cpa16(void* s, const void* g) {
    asm volatile("cp.async.cg.shared.global [%0], [%1], 16;\n"
                 :: "r"(smem_u32(s)), "l"(g));
}
__device__ __forceinline__ void cpa_commit() {
    asm volatile("cp.async.commit_group;\n");
}
__device__ __forceinline__ void ldm_x4(uint32_t& d0, uint32_t& d1,
                                       uint32_t& d2, uint32_t& d3,
                                       const void* p) {
    asm volatile("ldmatrix.sync.aligned.m8n8.x4.shared.b16 {%0,%1,%2,%3}, [%4];\n"
                 : "=r"(d0), "=r"(d1), "=r"(d2), "=r"(d3)
                 : "r"(smem_u32(p)));
}
__device__ __forceinline__ void ldm_x4_t(uint32_t& d0, uint32_t& d1,
                                         uint32_t& d2, uint32_t& d3,
                                         const void* p) {
    asm volatile("ldmatrix.sync.aligned.m8n8.x4.trans.shared.b16 {%0,%1,%2,%3}, [%4];\n"
                 : "=r"(d0), "=r"(d1), "=r"(d2), "=r"(d3)
                 : "r"(smem_u32(p)));
}
// bf16 mma (flash)
__device__ __forceinline__ void mma16816(float* c, const uint32_t* a,
                                         const uint32_t* b) {
    asm volatile("mma.sync.aligned.m16n8k16.row.col.f32.bf16.bf16.f32 "
                 "{%0,%1,%2,%3}, {%4,%5,%6,%7}, {%8,%9}, {%0,%1,%2,%3};\n"
                 : "+f"(c[0]), "+f"(c[1]), "+f"(c[2]), "+f"(c[3])
                 : "r"(a[0]), "r"(a[1]), "r"(a[2]), "r"(a[3]),
                   "r"(b[0]), "r"(b[1]));
}
// fp16 mma (weight GEMMs)
__device__ __forceinline__ void mma16816h(float* c, const uint32_t* a,
                                          const uint32_t* b) {
    asm volatile("mma.sync.aligned.m16n8k16.row.col.f32.f16.f16.f32 "
                 "{%0,%1,%2,%3}, {%4,%5,%6,%7}, {%8,%9}, {%0,%1,%2,%3};\n"
                 : "+f"(c[0]), "+f"(c[1]), "+f"(c[2]), "+f"(c[3])
                 : "r"(a[0]), "r"(a[1]), "r"(a[2]), "r"(a[3]),
                   "r"(b[0]), "r"(b[1]));
}
__device__ __forceinline__ uint32_t pack_hi(float a, float b) {
    __nv_bfloat162 v = __float22bfloat162_rn(make_float2(a, b));
    return *(uint32_t*)&v;
}
__device__ __forceinline__ uint32_t pack_lo(float a, float b) {
    float ra = a - __bfloat162float(__float2bfloat16_rn(a));
    float rb = b - __bfloat162float(__float2bfloat16_rn(b));
    __nv_bfloat162 v = __float22bfloat162_rn(make_float2(ra, rb));
    return *(uint32_t*)&v;
}
__device__ __forceinline__ uint32_t pack_hi_h(float a, float b) {
    __half2 v = __floats2half2_rn(a, b);
    return *(uint32_t*)&v;
}
__device__ __forceinline__ uint32_t pack_lo_h(float a, float b) {
    float ra = a - __half2float(__float2half_rn(a));
    float rb = b - __half2float(__float2half_rn(b));
    __half2 v = __floats2half2_rn(ra, rb);
    return *(uint32_t*)&v;
}

// ---------------- fp32 -> fp16 conversions ----------------------------------
__global__ __launch_bounds__(256)
void cvt_h2(const float4* __restrict__ src,
            __half2* __restrict__ hi, __half2* __restrict__ lo, int n4)
{
    int i = blockIdx.x * 256 + threadIdx.x;
    if (i >= n4) return;
    float4 v = src[i];
    __half h0 = __float2half_rn(v.x), h1 = __float2half_rn(v.y);
    __half h2 = __float2half_rn(v.z), h3 = __float2half_rn(v.w);
    float l0 = v.x - __half2float(h0), l1 = v.y - __half2float(h1);
    float l2 = v.z - __half2float(h2), l3 = v.w - __half2float(h3);
    __half2 a; a.x = h0; a.y = h1;
    __half2 b; b.x = h2; b.y = h3;
    hi[2 * i] = a; hi[2 * i + 1] = b;
    lo[2 * i] = __floats2half2_rn(l0, l1);
    lo[2 * i + 1] = __floats2half2_rn(l2, l3);
}

__global__ __launch_bounds__(256)
void cvt_h1(const float4* __restrict__ src, __half2* __restrict__ dst, int n4)
{
    int i = blockIdx.x * 256 + threadIdx.x;
    if (i >= n4) return;
    float4 v = src[i];
    dst[2 * i]     = __floats2half2_rn(v.x, v.y);
    dst[2 * i + 1] = __floats2half2_rn(v.z, v.w);
}

// ---------------- fp16x2 NT GEMM (HMMA, 128x128 tile, 2 CTAs/SM) ------------
// C[m,n] = sum_k (Ah+Al)[m,k]*B[n,k] + bias[n]
// A = fp16 hi+lo (exact to 2^-22), B = single fp16. 2 MMA passes.
// Stage: Ah(8K) Al(8K) B(8K) = 24K; 3 stages; 1 sync/iter.
#define GSTG 24576
#define GEMM_STAGES 3
#define GEMM_SMEM (GEMM_STAGES * GSTG)

__device__ __forceinline__ void gemm_iter(const char* s, float acc[4][4][4],
                                          int wm, int wn, int lane)
{
#pragma unroll
    for (int ks = 0; ks < 2; ks++) {
        const int ch = 2 * ks + (lane >> 4);
        uint32_t bq[4][2];
#pragma unroll
        for (int ip = 0; ip < 2; ip++) {
            int r   = wn * 32 + ip * 16 + ((lane >> 3) & 1) * 8 + (lane & 7);
            int off = r * 64 + ((ch ^ ((r >> 1) & 3)) << 4);
            uint32_t r0, r1, r2, r3;
            ldm_x4(r0, r1, r2, r3, s + 16384 + off);
            bq[2 * ip][0] = r0; bq[2 * ip + 1][0] = r1;
            bq[2 * ip][1] = r2; bq[2 * ip + 1][1] = r3;
        }
#pragma unroll
        for (int im = 0; im < 4; im++) {
            int r   = wm * 64 + im * 16 + ((lane >> 3) & 1) * 8 + (lane & 7);
            int off = r * 64 + ((ch ^ ((r >> 1) & 3)) << 4);
            uint32_t ah[4], al[4];
            ldm_x4(ah[0], ah[1], ah[2], ah[3], s + off);
            ldm_x4(al[0], al[1], al[2], al[3], s + 8192 + off);
#pragma unroll
            for (int in = 0; in < 4; in++) mma16816h(acc[im][in], ah, bq[in]);
#pragma unroll
            for (int in = 0; in < 4; in++) mma16816h(acc[im][in], al, bq[in]);
        }
    }
}

__global__ __launch_bounds__(256, 2)
void mma_gemm_nt(const __half* __restrict__ Ah,
                 const __half* __restrict__ Al,
                 const __half* __restrict__ Bq,
                 float* __restrict__ C,
                 const float* __restrict__ bias,
                 int N, int K)
{
    extern __shared__ __align__(16) char smem_dyn[];

    const int tid  = threadIdx.x;
    const int wid  = tid >> 5, lane = tid & 31;
    const int wm   = wid >> 2, wn = wid & 3;
    const int m0   = blockIdx.y * 128, n0 = blockIdx.x * 128;

    float acc[4][4][4];
#pragma unroll
    for (int a = 0; a < 4; a++)
#pragma unroll
        for (int b = 0; b < 4; b++)
#pragma unroll
            for (int c = 0; c < 4; c++) acc[a][b][c] = 0.f;

    const int niter = K / 32;

    auto load_stage = [&](char* s, int k0) {
#pragma unroll
        for (int t = 0; t < 6; t++) {
            int idx = t * 256 + tid;          // 0..1535
            int seg = idx >> 9;               // 0: Ah, 1: Al, 2: B
            int r2  = idx & 511;
            int row = r2 >> 2, j = r2 & 3;
            int off = row * 64 + ((j ^ ((row >> 1) & 3)) << 4);
            if (seg == 0)
                cpa16(s + off, Ah + (size_t)(m0 + row) * K + k0 + j * 8);
            else if (seg == 1)
                cpa16(s + 8192 + off, Al + (size_t)(m0 + row) * K + k0 + j * 8);
            else
                cpa16(s + 16384 + off, Bq + (size_t)(n0 + row) * K + k0 + j * 8);
        }
    };

    load_stage(smem_dyn, 0);           cpa_commit();
    load_stage(smem_dyn + GSTG, 32);   cpa_commit();

    for (int i = 0; i < niter; i++) {
        if (i + 1 < niter)
            asm volatile("cp.async.wait_group 1;\n");
        else
            asm volatile("cp.async.wait_group 0;\n");
        __syncthreads();
        if (i + 2 < niter) {
            load_stage(smem_dyn + (size_t)((i + 2) % GEMM_STAGES) * GSTG,
                       (i + 2) * 32);
            cpa_commit();
        }
        gemm_iter(smem_dyn + (size_t)(i % GEMM_STAGES) * GSTG,
                  acc, wm, wn, lane);
    }

#pragma unroll
    for (int im = 0; im < 4; im++) {
        int row = m0 + wm * 64 + im * 16 + (lane >> 2);
#pragma unroll
        for (int in = 0; in < 4; in++) {
            int col = n0 + wn * 32 + in * 8 + 2 * (lane & 3);
            float b0 = bias[col], b1 = bias[col + 1];
            float2 o0, o1;
            o0.x = acc[im][in][0] + b0; o0.y = acc[im][in][1] + b1;
            o1.x = acc[im][in][2] + b0; o1.y = acc[im][in][3] + b1;
            *(float2*)(C + (size_t)row * N + col)       = o0;
            *(float2*)(C + (size_t)(row + 8) * N + col) = o1;
        }
    }
}

// ---------------- LayerNorm + RoPE -> bf16 hi/lo Q(scaled), K, V ------------
__global__ __launch_bounds__(128)
void lnrope_kernel(const float* __restrict__ qkv,
                   const float* __restrict__ qw,
                   const float* __restrict__ kw,
                   __nv_bfloat16* __restrict__ Qh, __nv_bfloat16* __restrict__ Ql,
                   __nv_bfloat16* __restrict__ Kh, __nv_bfloat16* __restrict__ Kl,
                   __nv_bfloat16* __restrict__ Vh, __nv_bfloat16* __restrict__ Vl)
{
    const int t = blockIdx.x, h = blockIdx.y, c = threadIdx.x;
    const size_t base = (size_t)t * (3 * D_DIM) + (size_t)h * C_DIM + c;
    const float qv = qkv[base];
    const float kv = qkv[base + D_DIM];
    const float vv = qkv[base + 2 * D_DIM];

    __shared__ float red[4][4];
    float s0 = qv, s1 = qv * qv, s2 = kv, s3 = kv * kv;
#pragma unroll
    for (int o = 16; o; o >>= 1) {
        s0 += __shfl_xor_sync(0xffffffffu, s0, o);
        s1 += __shfl_xor_sync(0xffffffffu, s1, o);
        s2 += __shfl_xor_sync(0xffffffffu, s2, o);
        s3 += __shfl_xor_sync(0xffffffffu, s3, o);
    }
    const int w = c >> 5;
    if ((c & 31) == 0) { red[w][0] = s0; red[w][1] = s1; red[w][2] = s2; red[w][3] = s3; }
    __syncthreads();
    s0 = red[0][0] + red[1][0] + red[2][0] + red[3][0];
    s1 = red[0][1] + red[1][1] + red[2][1] + red[3][1];
    s2 = red[0][2] + red[1][2] + red[2][2] + red[3][2];
    s3 = red[0][3] + red[1][3] + red[2][3] + red[3][3];

    const float inv_n = 1.0f / (float)C_DIM;
    const float muq = s0 * inv_n, muk = s2 * inv_n;
    const float varq = s1 * inv_n - muq * muq;
    const float vark = s3 * inv_n - muk * muk;
    const float qn = (qv - muq) * rsqrtf(varq + 1e-6f) * qw[c];
    const float kn = (kv - muk) * rsqrtf(vark + 1e-6f) * kw[c];

    __shared__ float qs[C_DIM], ks[C_DIM];
    qs[c] = qn; ks[c] = kn;
    __syncthreads();

    const int i = c >> 1;
    const float inv_freq = powf(10000.f, -(float)(2 * i) / (float)C_DIM);
    float sn, cs;
    sincosf((float)t * inv_freq, &sn, &cs);
    const float qrot = (c & 1) ? qs[c - 1] : -qs[c + 1];
    const float krot = (c & 1) ? ks[c - 1] : -ks[c + 1];

    const float qsc = (qn * cs + qrot * sn) * 0.08838834764831845f;
    const float ksc = kn * cs + krot * sn;

    const size_t o = ((size_t)h * T_DIM + t) * C_DIM + c;
    __nv_bfloat16 b;
    b = __float2bfloat16_rn(qsc); Qh[o] = b;
    Ql[o] = __float2bfloat16_rn(qsc - __bfloat162float(b));
    b = __float2bfloat16_rn(ksc); Kh[o] = b;
    Kl[o] = __float2bfloat16_rn(ksc - __bfloat162float(b));
    b = __float2bfloat16_rn(vv);  Vh[o] = b;
    Vl[o] = __float2bfloat16_rn(vv - __bfloat162float(b));
}

// ---------------- tensor-core causal flash attention (HMMA bf16x3) ----------
// 256 threads = 8 warps; 128 q-rows per CTA; KV streamed in 64-row tiles,
// double-buffered. Epilogue writes fp16 hi/lo for the fp16 proj GEMM.
// smem: Q hi/lo 64K + 2 KV buffers (Kh,Kl,Vh,Vl 16K each) = 192K.
#define FA_SMEM (196608)

__global__ __launch_bounds__(256, 1)
void fa_kernel(const __nv_bfloat16* __restrict__ Qhg,
               const __nv_bfloat16* __restrict__ Qlg,
               const __nv_bfloat16* __restrict__ Khg,
               const __nv_bfloat16* __restrict__ Klg,
               const __nv_bfloat16* __restrict__ Vhg,
               const __nv_bfloat16* __restrict__ Vlg,
               __half* __restrict__ Ohg,
               __half* __restrict__ Olg)
{
    extern __shared__ __align__(16) char fsm[];
    char* sQh = fsm;
    char* sQl = fsm + 32768;
    // KV buffer b at fsm + 65536 + b*65536: Kh +0, Kl +16384, Vh +32768, Vl +49152

    const int m0 = (gridDim.x - 1 - blockIdx.x) * 128;   // heavy tiles first
    const int h  = blockIdx.y;
    const size_t hb = (size_t)h * T_DIM * C_DIM;

    const int tid  = threadIdx.x;
    const int w    = tid >> 5, lane = tid & 31;

#pragma unroll
    for (int i = 0; i < 8; i++) {
        int c = tid + i * 256;
        int row = c >> 4, ch = c & 15;
        int dst = row * 256 + ((ch ^ (row & 7)) << 4);
        size_t src = hb + (size_t)(m0 + row) * C_DIM + ch * 8;
        cpa16(sQh + dst, Qhg + src);
        cpa16(sQl + dst, Qlg + src);
    }
    cpa_commit();

    auto load_kv = [&](int buf, int kt) {
        char* b = fsm + 65536 + buf * 65536;
#pragma unroll
        for (int i = 0; i < 16; i++) {
            int idx = tid + i * 256;          // 0..4095
            int t   = idx >> 10;              // 0..3 (Kh,Kl,Vh,Vl)
            int r2  = idx & 1023;
            int row = r2 >> 4, ch = r2 & 15;
            int dst = t * 16384 + row * 256 + ((ch ^ (row & 7)) << 4);
            const __nv_bfloat16* srcp =
                (t == 0 ? Khg : t == 1 ? Klg : t == 2 ? Vhg : Vlg)
                + hb + (size_t)(kt + row) * C_DIM + ch * 8;
            cpa16(b + dst, srcp);
        }
    };

    float O[16][4];
#pragma unroll
    for (int f = 0; f < 16; f++)
#pragma unroll
        for (int x = 0; x < 4; x++) O[f][x] = 0.f;
    float mrow0 = -1e30f, mrow1 = -1e30f, lrow0 = 0.f, lrow1 = 0.f;

    const int arow = w * 16 + ((lane >> 3) & 1) * 8 + (lane & 7);
    const int achb = lane >> 4;

    const int nt = m0 / 64 + 2;               // kv tiles: kt = 0..m0+64

    load_kv(0, 0);
    cpa_commit();

    for (int j = 0; j < nt; j++) {
        const int kt = j * 64;
        asm volatile("cp.async.wait_group 0;\n");
        __syncthreads();
        if (j + 1 < nt) {
            load_kv((j + 1) & 1, kt + 64);
            cpa_commit();
        }

        const char* bKh = fsm + 65536 + (j & 1) * 65536;
        const char* bKl = bKh + 16384;
        const char* bVh = bKh + 32768;
        const char* bVl = bKh + 49152;

        // ---- S = Q.K^T over 64 kv cols (bf16x3) ----
        float S[8][4];
#pragma unroll
        for (int f = 0; f < 8; f++)
#pragma unroll
            for (int x = 0; x < 4; x++) S[f][x] = 0.f;

#pragma unroll
        for (int ks = 0; ks < 8; ks++) {
            const int ch = 2 * ks + achb;
            uint32_t aQh[4], aQl[4];
            ldm_x4(aQh[0], aQh[1], aQh[2], aQh[3],
                   sQh + arow * 256 + ((ch ^ (arow & 7)) << 4));
            ldm_x4(aQl[0], aQl[1], aQl[2], aQl[3],
                   sQl + arow * 256 + ((ch ^ (arow & 7)) << 4));
#pragma unroll
            for (int nb = 0; nb < 4; nb++) {
                const int brow = nb * 16 + ((lane >> 3) & 1) * 8 + (lane & 7);
                const int boff = brow * 256 + ((ch ^ (brow & 7)) << 4);
                uint32_t r0, r1, r2, r3;
                ldm_x4(r0, r1, r2, r3, bKh + boff);
                uint32_t blo[2] = {r0, r2}, bhi[2] = {r1, r3};
                mma16816(S[2 * nb],     aQh, blo);
                mma16816(S[2 * nb + 1], aQh, bhi);
                mma16816(S[2 * nb],     aQl, blo);
                mma16816(S[2 * nb + 1], aQl, bhi);
                ldm_x4(r0, r1, r2, r3, bKl + boff);
                uint32_t clo[2] = {r0, r2}, chi[2] = {r1, r3};
                mma16816(S[2 * nb],     aQh, clo);
                mma16816(S[2 * nb + 1], aQh, chi);
            }
        }

        // ---- causal mask ----
        const int row0 = m0 + w * 16 + (lane >> 2);
        if (kt + 64 > m0) {
#pragma unroll
            for (int f = 0; f < 8; f++) {
                const int col = kt + f * 8 + 2 * (lane & 3);
                if (col     > row0)     S[f][0] = -1e30f;
                if (col + 1 > row0)     S[f][1] = -1e30f;
                if (col     > row0 + 8) S[f][2] = -1e30f;
                if (col + 1 > row0 + 8) S[f][3] = -1e30f;
            }
        }

        // ---- online softmax ----
        float mx0 = -1e30f, mx1 = -1e30f;
#pragma unroll
        for (int f = 0; f < 8; f++) {
            mx0 = fmaxf(mx0, fmaxf(S[f][0], S[f][1]));
            mx1 = fmaxf(mx1, fmaxf(S[f][2], S[f][3]));
        }
        mx0 = fmaxf(mx0, __shfl_xor_sync(0xffffffffu, mx0, 1));
        mx0 = fmaxf(mx0, __shfl_xor_sync(0xffffffffu, mx0, 2));
        mx1 = fmaxf(mx1, __shfl_xor_sync(0xffffffffu, mx1, 1));
        mx1 = fmaxf(mx1, __shfl_xor_sync(0xffffffffu, mx1, 2));

        const float nm0 = fmaxf(mrow0, mx0);
        const float nm1 = fmaxf(mrow1, mx1);
        const float al0 = __expf(mrow0 - nm0);
        const float al1 = __expf(mrow1 - nm1);
        mrow0 = nm0; mrow1 = nm1;

        float sum0 = 0.f, sum1 = 0.f;
#pragma unroll
        for (int f = 0; f < 8; f++) {
            S[f][0] = __expf(S[f][0] - nm0);
            S[f][1] = __expf(S[f][1] - nm0);
            S[f][2] = __expf(S[f][2] - nm1);
            S[f][3] = __expf(S[f][3] - nm1);
            sum0 += S[f][0] + S[f][1];
            sum1 += S[f][2] + S[f][3];
        }
        sum0 += __shfl_xor_sync(0xffffffffu, sum0, 1);
        sum0 += __shfl_xor_sync(0xffffffffu, sum0, 2);
        sum1 += __shfl_xor_sync(0xffffffffu, sum1, 1);
        sum1 += __shfl_xor_sync(0xffffffffu, sum1, 2);
        lrow0 = lrow0 * al0 + sum0;
        lrow1 = lrow1 * al1 + sum1;

#pragma unroll
        for (int f = 0; f < 16; f++) {
            O[f][0] *= al0; O[f][1] *= al0;
            O[f][2] *= al1; O[f][3] *= al1;
        }

        // ---- O += P.V (bf16x3) ----
#pragma unroll
        for (int kb = 0; kb < 4; kb++) {
            uint32_t aPh[4], aPl[4];
            aPh[0] = pack_hi(S[2 * kb][0],     S[2 * kb][1]);
            aPh[1] = pack_hi(S[2 * kb][2],     S[2 * kb][3]);
            aPh[2] = pack_hi(S[2 * kb + 1][0], S[2 * kb + 1][1]);
            aPh[3] = pack_hi(S[2 * kb + 1][2], S[2 * kb + 1][3]);
            aPl[0] = pack_lo(S[2 * kb][0],     S[2 * kb][1]);
            aPl[1] = pack_lo(S[2 * kb][2],     S[2 * kb][3]);
            aPl[2] = pack_lo(S[2 * kb + 1][0], S[2 * kb + 1][1]);
            aPl[3] = pack_lo(S[2 * kb + 1][2], S[2 * kb + 1][3]);

            const int kvrow = kb * 16 + ((lane >> 3) & 1) * 8 + (lane & 7);
#pragma unroll
            for (int nb = 0; nb < 8; nb++) {
                const int chv  = 2 * nb + (lane >> 4);
                const int voff = kvrow * 256 + ((chv ^ (kvrow & 7)) << 4);
                uint32_t r0, r1, r2, r3;
                ldm_x4_t(r0, r1, r2, r3, bVh + voff);
                uint32_t blo[2] = {r0, r1}, bhi[2] = {r2, r3};
                mma16816(O[2 * nb],     aPh, blo);
                mma16816(O[2 * nb + 1], aPh, bhi);
                mma16816(O[2 * nb],     aPl, blo);
                mma16816(O[2 * nb + 1], aPl, bhi);
                ldm_x4_t(r0, r1, r2, r3, bVl + voff);
                uint32_t clo[2] = {r0, r1}, chi[2] = {r2, r3};
                mma16816(O[2 * nb],     aPh, clo);
                mma16816(O[2 * nb + 1], aPh, chi);
            }
        }
    }

    // ---- normalize + store fp16 hi/lo to [T, D] at column h*C ----
    const float inv0 = 1.f / lrow0;
    const float inv1 = 1.f / lrow1;
    const int orow = m0 + w * 16 + (lane >> 2);
#pragma unroll
    for (int f = 0; f < 16; f++) {
        const int col = h * C_DIM + f * 8 + 2 * (lane & 3);
        const float a0 = O[f][0] * inv0, a1 = O[f][1] * inv0;
        const float b0 = O[f][2] * inv1, b1 = O[f][3] * inv1;
        *(uint32_t*)(Ohg + (size_t)orow * D_DIM + col)       = pack_hi_h(a0, a1);
        *(uint32_t*)(Olg + (size_t)orow * D_DIM + col)       = pack_lo_h(a0, a1);
        *(uint32_t*)(Ohg + (size_t)(orow + 8) * D_DIM + col) = pack_hi_h(b0, b1);
        *(uint32_t*)(Olg + (size_t)(orow + 8) * D_DIM + col) = pack_lo_h(b0, b1);
    }
}

// ---------------------------------------------------------------------------
extern "C" void kernel_launch(void* const* d_in, const int* in_sizes, int n_in,
                              void* d_out, int out_size)
{
    const float* x      = (const float*)d_in[0];
    const float* W_attn = (const float*)d_in[1];
    const float* b_attn = (const float*)d_in[2];
    const float* W_proj = (const float*)d_in[3];
    const float* b_proj = (const float*)d_in[4];
    const float* q_ln_w = (const float*)d_in[5];
    const float* k_ln_w = (const float*)d_in[6];
    float* out = (float*)d_out;

    float *qkv;
    __half *xh, *xl, *wa, *wp, *aoh, *aol;
    __nv_bfloat16 *qh, *ql, *kh, *kl, *vh, *vl;
    cudaGetSymbolAddress((void**)&qkv, g_qkv);
    cudaGetSymbolAddress((void**)&xh,  g_xh);
    cudaGetSymbolAddress((void**)&xl,  g_xl);
    cudaGetSymbolAddress((void**)&wa,  g_wa);
    cudaGetSymbolAddress((void**)&wp,  g_wp);
    cudaGetSymbolAddress((void**)&aoh, g_aoh);
    cudaGetSymbolAddress((void**)&aol, g_aol);
    cudaGetSymbolAddress((void**)&qh,  g_qh);
    cudaGetSymbolAddress((void**)&ql,  g_ql);
    cudaGetSymbolAddress((void**)&kh,  g_kh);
    cudaGetSymbolAddress((void**)&kl,  g_kl);
    cudaGetSymbolAddress((void**)&vh,  g_vh);
    cudaGetSymbolAddress((void**)&vl,  g_vl);

    cudaFuncSetAttribute(mma_gemm_nt,
                         cudaFuncAttributeMaxDynamicSharedMemorySize, GEMM_SMEM);
    cudaFuncSetAttribute(fa_kernel,
                         cudaFuncAttributeMaxDynamicSharedMemorySize, FA_SMEM);

    const int n4_x  = T_DIM * D_DIM / 4;
    const int n4_wa = 3 * D_DIM * D_DIM / 4;
    const int n4_wp = D_DIM * D_DIM / 4;

    // 0) conversions: x -> fp16 hi/lo; weights -> single fp16
    cvt_h2<<<n4_x  / 256, 256>>>((const float4*)x,      (__half2*)xh, (__half2*)xl, n4_x);
    cvt_h1<<<n4_wa / 256, 256>>>((const float4*)W_attn, (__half2*)wa, n4_wa);
    cvt_h1<<<n4_wp / 256, 256>>>((const float4*)W_proj, (__half2*)wp, n4_wp);

    // 1) QKV = x @ W_attn^T + b_attn   (fp16x2, 2 MMA passes)
    mma_gemm_nt<<<dim3(3 * D_DIM / 128, T_DIM / 128), 256, GEMM_SMEM>>>(
        xh, xl, wa, qkv, b_attn, 3 * D_DIM, D_DIM);

    // 2) LayerNorm + RoPE -> bf16 hi/lo Q(scaled), K, V in [H,T,C]
    lnrope_kernel<<<dim3(T_DIM, H_DIM), 128>>>(qkv, q_ln_w, k_ln_w,
                                               qh, ql, kh, kl, vh, vl);

    // 3) fused causal flash attention (bf16x3) -> fp16 hi/lo ao [T, D]
    fa_kernel<<<dim3(T_DIM / 128, H_DIM), 256, FA_SMEM>>>(
        qh, ql, kh, kl, vh, vl, aoh, aol);

    // 4) out = ao @ W_proj^T + b_proj  (fp16x2)
    mma_gemm_nt<<<dim3(D_DIM / 128, T_DIM / 128), 256, GEMM_SMEM>>>(
        aoh, aol, wp, out, b_proj, D_DIM, D_DIM);
}

// round 16
// speedup vs baseline: 1.0053x; 1.0053x over previous
#include <cuda_runtime.h>
#include <cuda_bf16.h>
#include <cuda_fp16.h>
#include <math.h>
#include <stdint.h>
#include <stddef.h>

#define T_DIM 2048
#define D_DIM 2048
#define H_DIM 16
#define C_DIM 128

// ---------------- scratch (device globals; no runtime allocation) ----------
__device__ __align__(128) float g_qkv[(size_t)T_DIM * 3 * D_DIM];
__device__ __align__(128) __half g_xh [(size_t)T_DIM * D_DIM];
__device__ __align__(128) __half g_xl [(size_t)T_DIM * D_DIM];
__device__ __align__(128) __half g_wa [(size_t)3 * D_DIM * D_DIM];
__device__ __align__(128) __half g_wp [(size_t)D_DIM * D_DIM];
__device__ __align__(128) __half g_aoh[(size_t)T_DIM * D_DIM];
__device__ __align__(128) __half g_aol[(size_t)T_DIM * D_DIM];
__device__ __align__(128) __nv_bfloat16 g_qh[(size_t)H_DIM * T_DIM * C_DIM];
__device__ __align__(128) __nv_bfloat16 g_ql[(size_t)H_DIM * T_DIM * C_DIM];
__device__ __align__(128) __nv_bfloat16 g_kh[(size_t)H_DIM * T_DIM * C_DIM];
__device__ __align__(128) __nv_bfloat16 g_kl[(size_t)H_DIM * T_DIM * C_DIM];
__device__ __align__(128) __nv_bfloat16 g_vh[(size_t)H_DIM * T_DIM * C_DIM];
__device__ __align__(128) __nv_bfloat16 g_vl[(size_t)H_DIM * T_DIM * C_DIM];

// ---------------- asm helpers ----------------------------------------------
__device__ __forceinline__ uint32_t smem_u32(const void* p) {
    return (uint32_t)__cvta_generic_to_shared(p);
}
__device__ __forceinline__ void cpa16(void* s, const void* g) {
    asm volatile("cp.async.cg.shared.global [%0], [%1], 16;\n"
                 :: "r"(smem_u32(s)), "l"(g));
}
__device__ __forceinline__ void cpa_commit() {
    asm volatile("cp.async.commit_group;\n");
}
__device__ __forceinline__ void ldm_x4(uint32_t& d0, uint32_t& d1,
                                       uint32_t& d2, uint32_t& d3,
                                       const void* p) {
    asm volatile("ldmatrix.sync.aligned.m8n8.x4.shared.b16 {%0,%1,%2,%3}, [%4];\n"
                 : "=r"(d0), "=r"(d1), "=r"(d2), "=r"(d3)
                 : "r"(smem_u32(p)));
}
__device__ __forceinline__ void ldm_x4_t(uint32_t& d0, uint32_t& d1,
                                         uint32_t& d2, uint32_t& d3,
                                         const void* p) {
    asm volatile("ldmatrix.sync.aligned.m8n8.x4.trans.shared.b16 {%0,%1,%2,%3}, [%4];\n"
                 : "=r"(d0), "=r"(d1), "=r"(d2), "=r"(d3)
                 : "r"(smem_u32(p)));
}
// bf16 mma (flash)
__device__ __forceinline__ void mma16816(float* c, const uint32_t* a,
                                         const uint32_t* b) {
    asm volatile("mma.sync.aligned.m16n8k16.row.col.f32.bf16.bf16.f32 "
                 "{%0,%1,%2,%3}, {%4,%5,%6,%7}, {%8,%9}, {%0,%1,%2,%3};\n"
                 : "+f"(c[0]), "+f"(c[1]), "+f"(c[2]), "+f"(c[3])
                 : "r"(a[0]), "r"(a[1]), "r"(a[2]), "r"(a[3]),
                   "r"(b[0]), "r"(b[1]));
}
// fp16 mma (weight GEMMs)
__device__ __forceinline__ void mma16816h(float* c, const uint32_t* a,
                                          const uint32_t* b) {
    asm volatile("mma.sync.aligned.m16n8k16.row.col.f32.f16.f16.f32 "
                 "{%0,%1,%2,%3}, {%4,%5,%6,%7}, {%8,%9}, {%0,%1,%2,%3};\n"
                 : "+f"(c[0]), "+f"(c[1]), "+f"(c[2]), "+f"(c[3])
                 : "r"(a[0]), "r"(a[1]), "r"(a[2]), "r"(a[3]),
                   "r"(b[0]), "r"(b[1]));
}
__device__ __forceinline__ uint32_t pack_hi(float a, float b) {
    __nv_bfloat162 v = __float22bfloat162_rn(make_float2(a, b));
    return *(uint32_t*)&v;
}
__device__ __forceinline__ uint32_t pack_lo(float a, float b) {
    float ra = a - __bfloat162float(__float2bfloat16_rn(a));
    float rb = b - __bfloat162float(__float2bfloat16_rn(b));
    __nv_bfloat162 v = __float22bfloat162_rn(make_float2(ra, rb));
    return *(uint32_t*)&v;
}
__device__ __forceinline__ uint32_t pack_hi_h(float a, float b) {
    __half2 v = __floats2half2_rn(a, b);
    return *(uint32_t*)&v;
}
__device__ __forceinline__ uint32_t pack_lo_h(float a, float b) {
    float ra = a - __half2float(__float2half_rn(a));
    float rb = b - __half2float(__float2half_rn(b));
    __half2 v = __floats2half2_rn(ra, rb);
    return *(uint32_t*)&v;
}

// ---------------- fp32 -> fp16 conversions ----------------------------------
__global__ __launch_bounds__(256)
void cvt_h2(const float4* __restrict__ src,
            __half2* __restrict__ hi, __half2* __restrict__ lo, int n4)
{
    int i = blockIdx.x * 256 + threadIdx.x;
    if (i >= n4) return;
    float4 v = src[i];
    __half h0 = __float2half_rn(v.x), h1 = __float2half_rn(v.y);
    __half h2 = __float2half_rn(v.z), h3 = __float2half_rn(v.w);
    float l0 = v.x - __half2float(h0), l1 = v.y - __half2float(h1);
    float l2 = v.z - __half2float(h2), l3 = v.w - __half2float(h3);
    __half2 a; a.x = h0; a.y = h1;
    __half2 b; b.x = h2; b.y = h3;
    hi[2 * i] = a; hi[2 * i + 1] = b;
    lo[2 * i] = __floats2half2_rn(l0, l1);
    lo[2 * i + 1] = __floats2half2_rn(l2, l3);
}

__global__ __launch_bounds__(256)
void cvt_h1(const float4* __restrict__ src, __half2* __restrict__ dst, int n4)
{
    int i = blockIdx.x * 256 + threadIdx.x;
    if (i >= n4) return;
    float4 v = src[i];
    dst[2 * i]     = __floats2half2_rn(v.x, v.y);
    dst[2 * i + 1] = __floats2half2_rn(v.z, v.w);
}

// ---------------- fp16x2 NT GEMM (HMMA, 128x128 tile, 2 CTAs/SM) ------------
// C[m,n] = sum_k (Ah+Al)[m,k]*B[n,k] + bias[n]
// A = fp16 hi+lo (exact to 2^-22), B = single fp16. 2 MMA passes.
// Stage: Ah(8K) Al(8K) B(8K) = 24K; 3 stages; 1 sync/iter.
#define GSTG 24576
#define GEMM_STAGES 3
#define GEMM_SMEM (GEMM_STAGES * GSTG)

__device__ __forceinline__ void gemm_iter(const char* s, float acc[4][4][4],
                                          int wm, int wn, int lane)
{
#pragma unroll
    for (int ks = 0; ks < 2; ks++) {
        const int ch = 2 * ks + (lane >> 4);
        uint32_t bq[4][2];
#pragma unroll
        for (int ip = 0; ip < 2; ip++) {
            int r   = wn * 32 + ip * 16 + ((lane >> 3) & 1) * 8 + (lane & 7);
            int off = r * 64 + ((ch ^ ((r >> 1) & 3)) << 4);
            uint32_t r0, r1, r2, r3;
            ldm_x4(r0, r1, r2, r3, s + 16384 + off);
            bq[2 * ip][0] = r0; bq[2 * ip + 1][0] = r1;
            bq[2 * ip][1] = r2; bq[2 * ip + 1][1] = r3;
        }
#pragma unroll
        for (int im = 0; im < 4; im++) {
            int r   = wm * 64 + im * 16 + ((lane >> 3) & 1) * 8 + (lane & 7);
            int off = r * 64 + ((ch ^ ((r >> 1) & 3)) << 4);
            uint32_t ah[4], al[4];
            ldm_x4(ah[0], ah[1], ah[2], ah[3], s + off);
            ldm_x4(al[0], al[1], al[2], al[3], s + 8192 + off);
#pragma unroll
            for (int in = 0; in < 4; in++) mma16816h(acc[im][in], ah, bq[in]);
#pragma unroll
            for (int in = 0; in < 4; in++) mma16816h(acc[im][in], al, bq[in]);
        }
    }
}

__global__ __launch_bounds__(256, 2)
void mma_gemm_nt(const __half* __restrict__ Ah,
                 const __half* __restrict__ Al,
                 const __half* __restrict__ Bq,
                 float* __restrict__ C,
                 const float* __restrict__ bias,
                 int N, int K)
{
    extern __shared__ __align__(16) char smem_dyn[];

    const int tid  = threadIdx.x;
    const int wid  = tid >> 5, lane = tid & 31;
    const int wm   = wid >> 2, wn = wid & 3;
    const int m0   = blockIdx.y * 128, n0 = blockIdx.x * 128;

    float acc[4][4][4];
#pragma unroll
    for (int a = 0; a < 4; a++)
#pragma unroll
        for (int b = 0; b < 4; b++)
#pragma unroll
            for (int c = 0; c < 4; c++) acc[a][b][c] = 0.f;

    const int niter = K / 32;

    auto load_stage = [&](char* s, int k0) {
#pragma unroll
        for (int t = 0; t < 6; t++) {
            int idx = t * 256 + tid;          // 0..1535
            int seg = idx >> 9;               // 0: Ah, 1: Al, 2: B
            int r2  = idx & 511;
            int row = r2 >> 2, j = r2 & 3;
            int off = row * 64 + ((j ^ ((row >> 1) & 3)) << 4);
            if (seg == 0)
                cpa16(s + off, Ah + (size_t)(m0 + row) * K + k0 + j * 8);
            else if (seg == 1)
                cpa16(s + 8192 + off, Al + (size_t)(m0 + row) * K + k0 + j * 8);
            else
                cpa16(s + 16384 + off, Bq + (size_t)(n0 + row) * K + k0 + j * 8);
        }
    };

    load_stage(smem_dyn, 0);           cpa_commit();
    load_stage(smem_dyn + GSTG, 32);   cpa_commit();

    for (int i = 0; i < niter; i++) {
        if (i + 1 < niter)
            asm volatile("cp.async.wait_group 1;\n");
        else
            asm volatile("cp.async.wait_group 0;\n");
        __syncthreads();
        if (i + 2 < niter) {
            load_stage(smem_dyn + (size_t)((i + 2) % GEMM_STAGES) * GSTG,
                       (i + 2) * 32);
            cpa_commit();
        }
        gemm_iter(smem_dyn + (size_t)(i % GEMM_STAGES) * GSTG,
                  acc, wm, wn, lane);
    }

#pragma unroll
    for (int im = 0; im < 4; im++) {
        int row = m0 + wm * 64 + im * 16 + (lane >> 2);
#pragma unroll
        for (int in = 0; in < 4; in++) {
            int col = n0 + wn * 32 + in * 8 + 2 * (lane & 3);
            float b0 = bias[col], b1 = bias[col + 1];
            float2 o0, o1;
            o0.x = acc[im][in][0] + b0; o0.y = acc[im][in][1] + b1;
            o1.x = acc[im][in][2] + b0; o1.y = acc[im][in][3] + b1;
            *(float2*)(C + (size_t)row * N + col)       = o0;
            *(float2*)(C + (size_t)(row + 8) * N + col) = o1;
        }
    }
}

// ---------------- LayerNorm + RoPE -> bf16 hi/lo Q(scaled), K, V ------------
__global__ __launch_bounds__(128)
void lnrope_kernel(const float* __restrict__ qkv,
                   const float* __restrict__ qw,
                   const float* __restrict__ kw,
                   __nv_bfloat16* __restrict__ Qh, __nv_bfloat16* __restrict__ Ql,
                   __nv_bfloat16* __restrict__ Kh, __nv_bfloat16* __restrict__ Kl,
                   __nv_bfloat16* __restrict__ Vh, __nv_bfloat16* __restrict__ Vl)
{
    const int t = blockIdx.x, h = blockIdx.y, c = threadIdx.x;
    const size_t base = (size_t)t * (3 * D_DIM) + (size_t)h * C_DIM + c;
    const float qv = qkv[base];
    const float kv = qkv[base + D_DIM];
    const float vv = qkv[base + 2 * D_DIM];

    __shared__ float red[4][4];
    float s0 = qv, s1 = qv * qv, s2 = kv, s3 = kv * kv;
#pragma unroll
    for (int o = 16; o; o >>= 1) {
        s0 += __shfl_xor_sync(0xffffffffu, s0, o);
        s1 += __shfl_xor_sync(0xffffffffu, s1, o);
        s2 += __shfl_xor_sync(0xffffffffu, s2, o);
        s3 += __shfl_xor_sync(0xffffffffu, s3, o);
    }
    const int w = c >> 5;
    if ((c & 31) == 0) { red[w][0] = s0; red[w][1] = s1; red[w][2] = s2; red[w][3] = s3; }
    __syncthreads();
    s0 = red[0][0] + red[1][0] + red[2][0] + red[3][0];
    s1 = red[0][1] + red[1][1] + red[2][1] + red[3][1];
    s2 = red[0][2] + red[1][2] + red[2][2] + red[3][2];
    s3 = red[0][3] + red[1][3] + red[2][3] + red[3][3];

    const float inv_n = 1.0f / (float)C_DIM;
    const float muq = s0 * inv_n, muk = s2 * inv_n;
    const float varq = s1 * inv_n - muq * muq;
    const float vark = s3 * inv_n - muk * muk;
    const float qn = (qv - muq) * rsqrtf(varq + 1e-6f) * qw[c];
    const float kn = (kv - muk) * rsqrtf(vark + 1e-6f) * kw[c];

    __shared__ float qs[C_DIM], ks[C_DIM];
    qs[c] = qn; ks[c] = kn;
    __syncthreads();

    const int i = c >> 1;
    const float inv_freq = powf(10000.f, -(float)(2 * i) / (float)C_DIM);
    float sn, cs;
    sincosf((float)t * inv_freq, &sn, &cs);
    const float qrot = (c & 1) ? qs[c - 1] : -qs[c + 1];
    const float krot = (c & 1) ? ks[c - 1] : -ks[c + 1];

    const float qsc = (qn * cs + qrot * sn) * 0.08838834764831845f;
    const float ksc = kn * cs + krot * sn;

    const size_t o = ((size_t)h * T_DIM + t) * C_DIM + c;
    __nv_bfloat16 b;
    b = __float2bfloat16_rn(qsc); Qh[o] = b;
    Ql[o] = __float2bfloat16_rn(qsc - __bfloat162float(b));
    b = __float2bfloat16_rn(ksc); Kh[o] = b;
    Kl[o] = __float2bfloat16_rn(ksc - __bfloat162float(b));
    b = __float2bfloat16_rn(vv);  Vh[o] = b;
    Vl[o] = __float2bfloat16_rn(vv - __bfloat162float(b));
}

// ---------------- tensor-core causal flash attention (HMMA bf16x3) ----------
// 256 threads = 8 warps; 128 q-rows per CTA; KV streamed in 64-row tiles,
// double-buffered. Epilogue writes fp16 hi/lo for the fp16 proj GEMM.
// smem: Q hi/lo 64K + 2 KV buffers (Kh,Kl,Vh,Vl 16K each) = 192K.
#define FA_SMEM (196608)

__global__ __launch_bounds__(256, 1)
void fa_kernel(const __nv_bfloat16* __restrict__ Qhg,
               const __nv_bfloat16* __restrict__ Qlg,
               const __nv_bfloat16* __restrict__ Khg,
               const __nv_bfloat16* __restrict__ Klg,
               const __nv_bfloat16* __restrict__ Vhg,
               const __nv_bfloat16* __restrict__ Vlg,
               __half* __restrict__ Ohg,
               __half* __restrict__ Olg)
{
    extern __shared__ __align__(16) char fsm[];
    char* sQh = fsm;
    char* sQl = fsm + 32768;
    // KV buffer b at fsm + 65536 + b*65536: Kh +0, Kl +16384, Vh +32768, Vl +49152

    const int m0 = (gridDim.x - 1 - blockIdx.x) * 128;   // heavy tiles first
    const int h  = blockIdx.y;
    const size_t hb = (size_t)h * T_DIM * C_DIM;

    const int tid  = threadIdx.x;
    const int w    = tid >> 5, lane = tid & 31;

#pragma unroll
    for (int i = 0; i < 8; i++) {
        int c = tid + i * 256;
        int row = c >> 4, ch = c & 15;
        int dst = row * 256 + ((ch ^ (row & 7)) << 4);
        size_t src = hb + (size_t)(m0 + row) * C_DIM + ch * 8;
        cpa16(sQh + dst, Qhg + src);
        cpa16(sQl + dst, Qlg + src);
    }
    cpa_commit();

    auto load_kv = [&](int buf, int kt) {
        char* b = fsm + 65536 + buf * 65536;
#pragma unroll
        for (int i = 0; i < 16; i++) {
            int idx = tid + i * 256;          // 0..4095
            int t   = idx >> 10;              // 0..3 (Kh,Kl,Vh,Vl)
            int r2  = idx & 1023;
            int row = r2 >> 4, ch = r2 & 15;
            int dst = t * 16384 + row * 256 + ((ch ^ (row & 7)) << 4);
            const __nv_bfloat16* srcp =
                (t == 0 ? Khg : t == 1 ? Klg : t == 2 ? Vhg : Vlg)
                + hb + (size_t)(kt + row) * C_DIM + ch * 8;
            cpa16(b + dst, srcp);
        }
    };

    float O[16][4];
#pragma unroll
    for (int f = 0; f < 16; f++)
#pragma unroll
        for (int x = 0; x < 4; x++) O[f][x] = 0.f;
    float mrow0 = -1e30f, mrow1 = -1e30f, lrow0 = 0.f, lrow1 = 0.f;

    const int arow = w * 16 + ((lane >> 3) & 1) * 8 + (lane & 7);
    const int achb = lane >> 4;

    const int nt = m0 / 64 + 2;               // kv tiles: kt = 0..m0+64

    load_kv(0, 0);
    cpa_commit();

    for (int j = 0; j < nt; j++) {
        const int kt = j * 64;
        asm volatile("cp.async.wait_group 0;\n");
        __syncthreads();
        if (j + 1 < nt) {
            load_kv((j + 1) & 1, kt + 64);
            cpa_commit();
        }

        const char* bKh = fsm + 65536 + (j & 1) * 65536;
        const char* bKl = bKh + 16384;
        const char* bVh = bKh + 32768;
        const char* bVl = bKh + 49152;

        // ---- S = Q.K^T over 64 kv cols (bf16x3) ----
        float S[8][4];
#pragma unroll
        for (int f = 0; f < 8; f++)
#pragma unroll
            for (int x = 0; x < 4; x++) S[f][x] = 0.f;

#pragma unroll
        for (int ks = 0; ks < 8; ks++) {
            const int ch = 2 * ks + achb;
            uint32_t aQh[4], aQl[4];
            ldm_x4(aQh[0], aQh[1], aQh[2], aQh[3],
                   sQh + arow * 256 + ((ch ^ (arow & 7)) << 4));
            ldm_x4(aQl[0], aQl[1], aQl[2], aQl[3],
                   sQl + arow * 256 + ((ch ^ (arow & 7)) << 4));
#pragma unroll
            for (int nb = 0; nb < 4; nb++) {
                const int brow = nb * 16 + ((lane >> 3) & 1) * 8 + (lane & 7);
                const int boff = brow * 256 + ((ch ^ (brow & 7)) << 4);
                uint32_t r0, r1, r2, r3;
                ldm_x4(r0, r1, r2, r3, bKh + boff);
                uint32_t blo[2] = {r0, r2}, bhi[2] = {r1, r3};
                mma16816(S[2 * nb],     aQh, blo);
                mma16816(S[2 * nb + 1], aQh, bhi);
                mma16816(S[2 * nb],     aQl, blo);
                mma16816(S[2 * nb + 1], aQl, bhi);
                ldm_x4(r0, r1, r2, r3, bKl + boff);
                uint32_t clo[2] = {r0, r2}, chi[2] = {r1, r3};
                mma16816(S[2 * nb],     aQh, clo);
                mma16816(S[2 * nb + 1], aQh, chi);
            }
        }

        // ---- causal mask ----
        const int row0 = m0 + w * 16 + (lane >> 2);
        if (kt + 64 > m0) {
#pragma unroll
            for (int f = 0; f < 8; f++) {
                const int col = kt + f * 8 + 2 * (lane & 3);
                if (col     > row0)     S[f][0] = -1e30f;
                if (col + 1 > row0)     S[f][1] = -1e30f;
                if (col     > row0 + 8) S[f][2] = -1e30f;
                if (col + 1 > row0 + 8) S[f][3] = -1e30f;
            }
        }

        // ---- online softmax ----
        float mx0 = -1e30f, mx1 = -1e30f;
#pragma unroll
        for (int f = 0; f < 8; f++) {
            mx0 = fmaxf(mx0, fmaxf(S[f][0], S[f][1]));
            mx1 = fmaxf(mx1, fmaxf(S[f][2], S[f][3]));
        }
        mx0 = fmaxf(mx0, __shfl_xor_sync(0xffffffffu, mx0, 1));
        mx0 = fmaxf(mx0, __shfl_xor_sync(0xffffffffu, mx0, 2));
        mx1 = fmaxf(mx1, __shfl_xor_sync(0xffffffffu, mx1, 1));
        mx1 = fmaxf(mx1, __shfl_xor_sync(0xffffffffu, mx1, 2));

        const float nm0 = fmaxf(mrow0, mx0);
        const float nm1 = fmaxf(mrow1, mx1);
        const float al0 = __expf(mrow0 - nm0);
        const float al1 = __expf(mrow1 - nm1);
        mrow0 = nm0; mrow1 = nm1;

        float sum0 = 0.f, sum1 = 0.f;
#pragma unroll
        for (int f = 0; f < 8; f++) {
            S[f][0] = __expf(S[f][0] - nm0);
            S[f][1] = __expf(S[f][1] - nm0);
            S[f][2] = __expf(S[f][2] - nm1);
            S[f][3] = __expf(S[f][3] - nm1);
            sum0 += S[f][0] + S[f][1];
            sum1 += S[f][2] + S[f][3];
        }
        sum0 += __shfl_xor_sync(0xffffffffu, sum0, 1);
        sum0 += __shfl_xor_sync(0xffffffffu, sum0, 2);
        sum1 += __shfl_xor_sync(0xffffffffu, sum1, 1);
        sum1 += __shfl_xor_sync(0xffffffffu, sum1, 2);
        lrow0 = lrow0 * al0 + sum0;
        lrow1 = lrow1 * al1 + sum1;

#pragma unroll
        for (int f = 0; f < 16; f++) {
            O[f][0] *= al0; O[f][1] *= al0;
            O[f][2] *= al1; O[f][3] *= al1;
        }

        // ---- O += P.V (bf16x3) ----
#pragma unroll
        for (int kb = 0; kb < 4; kb++) {
            uint32_t aPh[4], aPl[4];
            aPh[0] = pack_hi(S[2 * kb][0],     S[2 * kb][1]);
            aPh[1] = pack_hi(S[2 * kb][2],     S[2 * kb][3]);
            aPh[2] = pack_hi(S[2 * kb + 1][0], S[2 * kb + 1][1]);
            aPh[3] = pack_hi(S[2 * kb + 1][2], S[2 * kb + 1][3]);
            aPl[0] = pack_lo(S[2 * kb][0],     S[2 * kb][1]);
            aPl[1] = pack_lo(S[2 * kb][2],     S[2 * kb][3]);
            aPl[2] = pack_lo(S[2 * kb + 1][0], S[2 * kb + 1][1]);
            aPl[3] = pack_lo(S[2 * kb + 1][2], S[2 * kb + 1][3]);

            const int kvrow = kb * 16 + ((lane >> 3) & 1) * 8 + (lane & 7);
#pragma unroll
            for (int nb = 0; nb < 8; nb++) {
                const int chv  = 2 * nb + (lane >> 4);
                const int voff = kvrow * 256 + ((chv ^ (kvrow & 7)) << 4);
                uint32_t r0, r1, r2, r3;
                ldm_x4_t(r0, r1, r2, r3, bVh + voff);
                uint32_t blo[2] = {r0, r1}, bhi[2] = {r2, r3};
                mma16816(O[2 * nb],     aPh, blo);
                mma16816(O[2 * nb + 1], aPh, bhi);
                mma16816(O[2 * nb],     aPl, blo);
                mma16816(O[2 * nb + 1], aPl, bhi);
                ldm_x4_t(r0, r1, r2, r3, bVl + voff);
                uint32_t clo[2] = {r0, r1}, chi[2] = {r2, r3};
                mma16816(O[2 * nb],     aPh, clo);
                mma16816(O[2 * nb + 1], aPh, chi);
            }
        }
    }

    // ---- normalize + store fp16 hi/lo to [T, D] at column h*C ----
    const float inv0 = 1.f / lrow0;
    const float inv1 = 1.f / lrow1;
    const int orow = m0 + w * 16 + (lane >> 2);
#pragma unroll
    for (int f = 0; f < 16; f++) {
        const int col = h * C_DIM + f * 8 + 2 * (lane & 3);
        const float a0 = O[f][0] * inv0, a1 = O[f][1] * inv0;
        const float b0 = O[f][2] * inv1, b1 = O[f][3] * inv1;
        *(uint32_t*)(Ohg + (size_t)orow * D_DIM + col)       = pack_hi_h(a0, a1);
        *(uint32_t*)(Olg + (size_t)orow * D_DIM + col)       = pack_lo_h(a0, a1);
        *(uint32_t*)(Ohg + (size_t)(orow + 8) * D_DIM + col) = pack_hi_h(b0, b1);
        *(uint32_t*)(Olg + (size_t)(orow + 8) * D_DIM + col) = pack_lo_h(b0, b1);
    }
}

// ---------------------------------------------------------------------------
extern "C" void kernel_launch(void* const* d_in, const int* in_sizes, int n_in,
                              void* d_out, int out_size)
{
    const float* x      = (const float*)d_in[0];
    const float* W_attn = (const float*)d_in[1];
    const float* b_attn = (const float*)d_in[2];
    const float* W_proj = (const float*)d_in[3];
    const float* b_proj = (const float*)d_in[4];
    const float* q_ln_w = (const float*)d_in[5];
    const float* k_ln_w = (const float*)d_in[6];
    float* out = (float*)d_out;

    float *qkv;
    __half *xh, *xl, *wa, *wp, *aoh, *aol;
    __nv_bfloat16 *qh, *ql, *kh, *kl, *vh, *vl;
    cudaGetSymbolAddress((void**)&qkv, g_qkv);
    cudaGetSymbolAddress((void**)&xh,  g_xh);
    cudaGetSymbolAddress((void**)&xl,  g_xl);
    cudaGetSymbolAddress((void**)&wa,  g_wa);
    cudaGetSymbolAddress((void**)&wp,  g_wp);
    cudaGetSymbolAddress((void**)&aoh, g_aoh);
    cudaGetSymbolAddress((void**)&aol, g_aol);
    cudaGetSymbolAddress((void**)&qh,  g_qh);
    cudaGetSymbolAddress((void**)&ql,  g_ql);
    cudaGetSymbolAddress((void**)&kh,  g_kh);
    cudaGetSymbolAddress((void**)&kl,  g_kl);
    cudaGetSymbolAddress((void**)&vh,  g_vh);
    cudaGetSymbolAddress((void**)&vl,  g_vl);

    cudaFuncSetAttribute(mma_gemm_nt,
                         cudaFuncAttributeMaxDynamicSharedMemorySize, GEMM_SMEM);
    cudaFuncSetAttribute(fa_kernel,
                         cudaFuncAttributeMaxDynamicSharedMemorySize, FA_SMEM);

    const int n4_x  = T_DIM * D_DIM / 4;
    const int n4_wa = 3 * D_DIM * D_DIM / 4;
    const int n4_wp = D_DIM * D_DIM / 4;

    // 0) conversions: x -> fp16 hi/lo; weights -> single fp16
    cvt_h2<<<n4_x  / 256, 256>>>((const float4*)x,      (__half2*)xh, (__half2*)xl, n4_x);
    cvt_h1<<<n4_wa / 256, 256>>>((const float4*)W_attn, (__half2*)wa, n4_wa);
    cvt_h1<<<n4_wp / 256, 256>>>((const float4*)W_proj, (__half2*)wp, n4_wp);

    // 1) QKV = x @ W_attn^T + b_attn   (fp16x2, 2 MMA passes)
    mma_gemm_nt<<<dim3(3 * D_DIM / 128, T_DIM / 128), 256, GEMM_SMEM>>>(
        xh, xl, wa, qkv, b_attn, 3 * D_DIM, D_DIM);

    // 2) LayerNorm + RoPE -> bf16 hi/lo Q(scaled), K, V in [H,T,C]
    lnrope_kernel<<<dim3(T_DIM, H_DIM), 128>>>(qkv, q_ln_w, k_ln_w,
                                               qh, ql, kh, kl, vh, vl);

    // 3) fused causal flash attention (bf16x3) -> fp16 hi/lo ao [T, D]
    fa_kernel<<<dim3(T_DIM / 128, H_DIM), 256, FA_SMEM>>>(
        qh, ql, kh, kl, vh, vl, aoh, aol);

    // 4) out = ao @ W_proj^T + b_proj  (fp16x2)
    mma_gemm_nt<<<dim3(D_DIM / 128, T_DIM / 128), 256, GEMM_SMEM>>>(
        aoh, aol, wp, out, b_proj, D_DIM, D_DIM);
}